// round 3
// baseline (speedup 1.0000x reference)
#include <cuda_runtime.h>
#include <math.h>

#define HH 48
#define WW 160
#define PIX 7680            // HH*WW
#define NPAD 8192

// ---------------- scratch (device globals; no allocation) ----------------
__device__ float g_hw1[16*128*9];   // packed head conv1 weights
__device__ float g_hb1[16];         // packed head conv1 bias
__device__ float g_h1raw[16*PIX];   // head conv1 partial sums (atomic)
__device__ float g_h1act[16*PIX];   // gelu(head conv1)
__device__ float g_feat1[128*PIX];  // fl1 output
__device__ float g_gsfeat[64*PIX];  // fl2 output (gaussian features, [c][p])
__device__ float g_u[PIX], g_v[PIX], g_Ac[PIX], g_Bc[PIX], g_Cc[PIX], g_op[PIX];
__device__ unsigned g_zkey[PIX];
__device__ unsigned g_order[PIX];
__device__ float g_us[PIX], g_vs[PIX], g_As[PIX], g_Bs[PIX], g_Cs[PIX], g_os[PIX];
__device__ float g_featS[PIX*64];   // sorted features [n][64]
__device__ float g_lev[64*PIX];     // rasterized level [c][p]

// ---------------- helpers ----------------
template<int A>
__device__ __forceinline__ float actf(float v){
    if (A == 1) { // ELU
        return v > 0.f ? v : expm1f(v);
    }
    if (A == 2) { // GELU (tanh approx, jax default)
        float v3 = v*v*v;
        return 0.5f*v*(1.f + tanhf(0.7978845608028654f*(v + 0.044715f*v3)));
    }
    return v;
}

// ---------------- generic tiled 3x3 conv ----------------
// Tile: 32 (x) by 8 (y) pixels, 16 output channels per block.
// 128 threads: tco=tid>>6 (2 groups of 8 co), ty=(tid&63)>>3, tx=tid&7 (4 px each).
// PADM: 0=reflect, 1=edge.  ACT: 0=raw atomic partial, 1=ELU, 2=GELU.
// CSPLIT: split input channels across gridDim.z (atomicAdd partials).
template<int CIN, int PADM, int ACT, int CSPLIT>
__global__ __launch_bounds__(128)
void conv3x3_t(const float* __restrict__ in, const float* __restrict__ wgt,
               const float* __restrict__ bias, float* __restrict__ out)
{
    __shared__ float s_in[8*10*37];   // 8 cin x 10 rows x 37 (pad) cols
    __shared__ float s_w[16*72];      // 16 co x 8 cin x 9 taps

    const int tid = threadIdx.x;
    const int tco = tid >> 6;
    const int r   = tid & 63;
    const int ty  = r >> 3;
    const int tx  = r & 7;
    const int x0  = blockIdx.x * 32;
    const int y0  = blockIdx.y * 8;
    const int ncog = gridDim.z / CSPLIT;
    const int cog  = blockIdx.z % ncog;
    const int csp  = blockIdx.z / ncog;
    const int cin0 = csp * (CIN / CSPLIT);
    const int coB  = cog * 16;

    float acc[8][4];
    #pragma unroll
    for (int a = 0; a < 8; a++)
        #pragma unroll
        for (int b = 0; b < 4; b++) acc[a][b] = 0.f;

    const int CHUNKS = CIN / CSPLIT / 8;
    for (int ch = 0; ch < CHUNKS; ch++) {
        const int cb = cin0 + ch * 8;
        __syncthreads();
        // load input tile (10 x 34 per cin)
        for (int e = tid; e < 2720; e += 128) {
            int ci = e / 340; int rem = e - ci * 340;
            int rr = rem / 34; int cc = rem - rr * 34;
            int yi = y0 - 1 + rr, xi = x0 - 1 + cc;
            if (PADM == 0) { // reflect
                yi = yi < 0 ? -yi : (yi >= HH ? 2*HH-2-yi : yi);
                xi = xi < 0 ? -xi : (xi >= WW ? 2*WW-2-xi : xi);
            } else {         // edge
                yi = yi < 0 ? 0 : (yi >= HH ? HH-1 : yi);
                xi = xi < 0 ? 0 : (xi >= WW ? WW-1 : xi);
            }
            s_in[ci*370 + rr*37 + cc] = in[(cb + ci)*PIX + yi*WW + xi];
        }
        // load weights
        for (int e = tid; e < 1152; e += 128) {
            int co = e / 72; int rem = e - co * 72;
            s_w[e] = wgt[(coB + co)*(CIN*9) + cb*9 + rem];
        }
        __syncthreads();

        #pragma unroll
        for (int ci = 0; ci < 8; ci++) {
            float xv[3][6];
            #pragma unroll
            for (int kh = 0; kh < 3; kh++)
                #pragma unroll
                for (int c2 = 0; c2 < 6; c2++)
                    xv[kh][c2] = s_in[ci*370 + (ty+kh)*37 + tx*4 + c2];
            #pragma unroll
            for (int kh = 0; kh < 3; kh++)
                #pragma unroll
                for (int kw = 0; kw < 3; kw++) {
                    #pragma unroll
                    for (int co = 0; co < 8; co++) {
                        float wv = s_w[(tco*8+co)*72 + ci*9 + kh*3 + kw];
                        #pragma unroll
                        for (int px = 0; px < 4; px++)
                            acc[co][px] = fmaf(xv[kh][kw+px], wv, acc[co][px]);
                    }
                }
        }
    }

    const int x = x0 + tx*4, y = y0 + ty;
    #pragma unroll
    for (int co = 0; co < 8; co++) {
        const int cg = coB + tco*8 + co;
        float* op = out + cg*PIX + y*WW + x;
        if (CSPLIT > 1) {
            #pragma unroll
            for (int px = 0; px < 4; px++) atomicAdd(op + px, acc[co][px]);
        } else {
            const float b = bias[cg];
            float4 vv;
            vv.x = actf<ACT>(acc[co][0] + b);
            vv.y = actf<ACT>(acc[co][1] + b);
            vv.z = actf<ACT>(acc[co][2] + b);
            vv.w = actf<ACT>(acc[co][3] + b);
            *reinterpret_cast<float4*>(op) = vv;
        }
    }
}

// ---------------- pack head conv1 weights (rot8 + scl6 + opa2) ----------------
__global__ void pack_heads_kernel(const float* __restrict__ rw1, const float* __restrict__ sw1,
                                  const float* __restrict__ ow1, const float* __restrict__ rb1,
                                  const float* __restrict__ sb1, const float* __restrict__ ob1)
{
    int i = blockIdx.x * 256 + threadIdx.x;
    if (i < 16*1152) {
        int co = i / 1152, rem = i - co*1152;
        float v;
        if (co < 8)       v = rw1[co*1152 + rem];
        else if (co < 14) v = sw1[(co-8)*1152 + rem];
        else              v = ow1[(co-14)*1152 + rem];
        g_hw1[i] = v;
    }
    if (i < 16) {
        float b;
        if (i < 8)       b = rb1[i];
        else if (i < 14) b = sb1[i-8];
        else             b = ob1[i-14];
        g_hb1[i] = b;
    }
}

__global__ void zero_h1raw_kernel()
{
    int i = blockIdx.x * 256 + threadIdx.x;
    if (i < 16*PIX) g_h1raw[i] = 0.f;
}

__global__ void h1_epilogue_kernel()
{
    int i = blockIdx.x * 256 + threadIdx.x;
    if (i < 16*PIX) {
        int c = i / PIX;
        float v = g_h1raw[i] + g_hb1[c];
        float v3 = v*v*v;
        g_h1act[i] = 0.5f*v*(1.f + tanhf(0.7978845608028654f*(v + 0.044715f*v3)));
    }
}

// ---------------- head conv2 + gaussian precompute ----------------
__global__ void heads2_kernel(const float* __restrict__ disp,
                              const float* __restrict__ invK, const float* __restrict__ Kmat,
                              const float* __restrict__ rw2, const float* __restrict__ rb2,
                              const float* __restrict__ sw2, const float* __restrict__ sb2,
                              const float* __restrict__ ow2, const float* __restrict__ ob2)
{
    int p = blockIdx.x * 256 + threadIdx.x;
    if (p >= PIX) return;
    int yy = p / WW, xx = p - yy*WW;

    int nb[9];
    #pragma unroll
    for (int kh = 0; kh < 3; kh++) {
        int yi = yy - 1 + kh; yi = yi < 0 ? 0 : (yi >= HH ? HH-1 : yi);  // edge pad
        #pragma unroll
        for (int kw = 0; kw < 3; kw++) {
            int xi = xx - 1 + kw; xi = xi < 0 ? 0 : (xi >= WW ? WW-1 : xi);
            nb[kh*3+kw] = yi*WW + xi;
        }
    }

    // rot head conv2: 8 -> 4
    float q[4] = { rb2[0], rb2[1], rb2[2], rb2[3] };
    for (int ci = 0; ci < 8; ci++) {
        #pragma unroll
        for (int t = 0; t < 9; t++) {
            float a = g_h1act[ci*PIX + nb[t]];
            #pragma unroll
            for (int k = 0; k < 4; k++) q[k] = fmaf(a, rw2[k*72 + ci*9 + t], q[k]);
        }
    }
    float nrm = sqrtf(q[0]*q[0] + q[1]*q[1] + q[2]*q[2] + q[3]*q[3]);
    nrm = fmaxf(nrm, 1e-12f);
    float inr = 1.f / nrm;
    float qw = q[0]*inr, qx = q[1]*inr, qy = q[2]*inr, qz = q[3]*inr;

    // scale head conv2: 6 -> 3, abs
    float s3[3] = { sb2[0], sb2[1], sb2[2] };
    for (int ci = 0; ci < 6; ci++) {
        #pragma unroll
        for (int t = 0; t < 9; t++) {
            float a = g_h1act[(8+ci)*PIX + nb[t]];
            #pragma unroll
            for (int k = 0; k < 3; k++) s3[k] = fmaf(a, sw2[k*54 + ci*9 + t], s3[k]);
        }
    }
    float s0 = fabsf(s3[0]), s1 = fabsf(s3[1]), s2 = fabsf(s3[2]);

    // opacity head conv2: 2 -> 1, sigmoid
    float ov = ob2[0];
    for (int ci = 0; ci < 2; ci++) {
        #pragma unroll
        for (int t = 0; t < 9; t++)
            ov = fmaf(g_h1act[(14+ci)*PIX + nb[t]], ow2[ci*9 + t], ov);
    }
    float opa = 1.f / (1.f + expf(-ov));

    // depth & position
    float dsp = disp[p];
    float scaled = (1.f/100.f) + (1.f/0.1f - 1.f/100.f) * dsp;
    float d = 1.f / scaled;
    d = fminf(fmaxf(d, 0.1f), 100.f);
    float fxp = (float)xx, fyp = (float)yy;
    float X = (invK[0]*fxp + invK[1]*fyp + invK[2])  * d;
    float Y = (invK[4]*fxp + invK[5]*fyp + invK[6])  * d;
    float Z = (invK[8]*fxp + invK[9]*fyp + invK[10]) * d;

    float fx = Kmat[0], fy = Kmat[5], cx = Kmat[2], cy = Kmat[6];

    // quat -> rot, column-scaled
    float r00 = 1.f - 2.f*(qy*qy + qz*qz), r01 = 2.f*(qx*qy - qw*qz), r02 = 2.f*(qx*qz + qw*qy);
    float r10 = 2.f*(qx*qy + qw*qz), r11 = 1.f - 2.f*(qx*qx + qz*qz), r12 = 2.f*(qy*qz - qw*qx);
    float r20 = 2.f*(qx*qz - qw*qy), r21 = 2.f*(qy*qz + qw*qx), r22 = 1.f - 2.f*(qx*qx + qy*qy);
    float m00 = r00*s0, m01 = r01*s1, m02 = r02*s2;
    float m10 = r10*s0, m11 = r11*s1, m12 = r12*s2;
    float m20 = r20*s0, m21 = r21*s1, m22 = r22*s2;
    float S00 = m00*m00 + m01*m01 + m02*m02;
    float S01 = m00*m10 + m01*m11 + m02*m12;
    float S02 = m00*m20 + m01*m21 + m02*m22;
    float S11 = m10*m10 + m11*m11 + m12*m12;
    float S12 = m10*m20 + m11*m21 + m12*m22;
    float S22 = m20*m20 + m21*m21 + m22*m22;

    float iz = 1.f / Z;
    float j00 = fx*iz,  j02 = -fx*X*iz*iz;
    float j11 = fy*iz,  j12 = -fy*Y*iz*iz;
    float t00 = j00*S00 + j02*S02;
    float t01 = j00*S01 + j02*S12;
    float t02 = j00*S02 + j02*S22;
    float cov00 = t00*j00 + t02*j02;
    float cov01 = t01*j11 + t02*j12;
    float t11 = j11*S11 + j12*S12;
    float t12 = j11*S12 + j12*S22;
    float cov11 = t11*j11 + t12*j12;

    float a = cov00 + 0.3f, b = cov01, c = cov11 + 0.3f;
    float det = a*c - b*b;
    float idet = 1.f / det;

    g_u[p]  = fx*X*iz + cx;
    g_v[p]  = fy*Y*iz + cy;
    g_Ac[p] = c * idet;
    g_Bc[p] = -b * idet;
    g_Cc[p] = a * idet;
    g_op[p] = opa;
    g_zkey[p] = __float_as_uint(Z);   // Z > 0 for this camera
}

// ---------------- bitonic sort (single block, 8192 slots, 48KB smem) ----------------
__global__ __launch_bounds__(1024) void sort_kernel()
{
    __shared__ unsigned skey[NPAD];
    __shared__ unsigned short sidx[NPAD];
    const int tid = threadIdx.x;
    for (int i = tid; i < NPAD; i += 1024) {
        skey[i] = (i < PIX) ? g_zkey[i] : 0xFFFFFFFFu;
        sidx[i] = (unsigned short)i;
    }
    __syncthreads();
    for (int k = 2; k <= NPAD; k <<= 1) {
        for (int j = k >> 1; j > 0; j >>= 1) {
            for (int i = tid; i < NPAD; i += 1024) {
                int ixj = i ^ j;
                if (ixj > i) {
                    bool up = ((i & k) == 0);
                    unsigned a = skey[i], b = skey[ixj];
                    unsigned short ia = sidx[i], ib = sidx[ixj];
                    bool gt = (a > b) || (a == b && ia > ib);
                    if (gt == up) {
                        skey[i] = b; skey[ixj] = a;
                        sidx[i] = ib; sidx[ixj] = ia;
                    }
                }
            }
            __syncthreads();
        }
    }
    for (int i = tid; i < PIX; i += 1024) g_order[i] = sidx[i];
}

// ---------------- gather sorted SoA ----------------
__global__ void gather_kernel()
{
    int idx = blockIdx.x * 256 + threadIdx.x;
    if (idx >= PIX*64) return;
    int n = idx >> 6, c = idx & 63;
    unsigned p = g_order[n];
    g_featS[idx] = g_gsfeat[c*PIX + p];
    if (c == 0) g_us[n] = g_u[p];
    else if (c == 1) g_vs[n] = g_v[p];
    else if (c == 2) g_As[n] = g_Ac[p];
    else if (c == 3) g_Bs[n] = g_Bc[p];
    else if (c == 4) g_Cs[n] = g_Cc[p];
    else if (c == 5) g_os[n] = g_op[p];
}

// ---------------- rasterize: warp per pixel, front-to-back compositing ----------------
__global__ __launch_bounds__(512) void raster_kernel()
{
    __shared__ float su[512], sv[512], sA[512], sB[512], sC[512], so[512];
    const int tid = threadIdx.x;
    const int warp = tid >> 5, lane = tid & 31;
    const int p = blockIdx.x * 16 + warp;
    const float gx = (float)(p % WW), gy = (float)(p / WW);

    float T = 1.f, acc0 = 0.f, acc1 = 0.f;
    bool done = false;

    for (int base = 0; base < PIX; base += 512) {
        __syncthreads();
        su[tid] = g_us[base + tid];
        sv[tid] = g_vs[base + tid];
        sA[tid] = g_As[base + tid];
        sB[tid] = g_Bs[base + tid];
        sC[tid] = g_Cs[base + tid];
        so[tid] = g_os[base + tid];
        __syncthreads();
        if (done) continue;

        for (int sub = 0; sub < 16 && !done; sub++) {
            int gl = sub*32 + lane;
            float dx = gx - su[gl], dy = gy - sv[gl];
            float pw = -0.5f*(sA[gl]*dx*dx + sC[gl]*dy*dy) - sB[gl]*dx*dy;
            float alpha = 0.f;
            if (pw <= 0.f && pw > -20.f)
                alpha = fminf(so[gl]*__expf(pw), 0.99f);

            unsigned any = __ballot_sync(0xffffffffu, alpha > 0.f);
            if (!any) continue;

            float one = 1.f - alpha;
            float pr = one;
            #pragma unroll
            for (int off = 1; off < 32; off <<= 1) {
                float t2 = __shfl_up_sync(0xffffffffu, pr, off);
                if (lane >= off) pr *= t2;
            }
            float excl = __shfl_up_sync(0xffffffffu, pr, 1);
            if (lane == 0) excl = 1.f;
            float wgt = alpha * T * excl;
            float tot = __shfl_sync(0xffffffffu, pr, 31);

            unsigned m = __ballot_sync(0xffffffffu, wgt > 1e-9f);
            while (m) {
                int l = __ffs(m) - 1; m &= m - 1;
                float wl = __shfl_sync(0xffffffffu, wgt, l);
                const float* fp = g_featS + (base + sub*32 + l)*64;
                acc0 = fmaf(wl, fp[lane],      acc0);
                acc1 = fmaf(wl, fp[lane + 32], acc1);
            }
            T *= tot;
            if (T < 1e-7f) done = true;
        }
    }
    g_lev[lane*PIX + p]      = acc0;
    g_lev[(lane+32)*PIX + p] = acc1;
}

// ---------------- launch ----------------
extern "C" void kernel_launch(void* const* d_in, const int* in_sizes, int n_in,
                              void* d_out, int out_size)
{
    const float* init_feature = (const float*)d_in[0];
    const float* disp   = (const float*)d_in[1];
    const float* invK   = (const float*)d_in[2];
    const float* Kmat   = (const float*)d_in[3];
    const float* rot_w1 = (const float*)d_in[4];
    const float* rot_b1 = (const float*)d_in[5];
    const float* rot_w2 = (const float*)d_in[6];
    const float* rot_b2 = (const float*)d_in[7];
    const float* scl_w1 = (const float*)d_in[8];
    const float* scl_b1 = (const float*)d_in[9];
    const float* scl_w2 = (const float*)d_in[10];
    const float* scl_b2 = (const float*)d_in[11];
    const float* opa_w1 = (const float*)d_in[12];
    const float* opa_b1 = (const float*)d_in[13];
    const float* opa_w2 = (const float*)d_in[14];
    const float* opa_b2 = (const float*)d_in[15];
    const float* fl_w1  = (const float*)d_in[16];
    const float* fl_b1  = (const float*)d_in[17];
    const float* fl_w2  = (const float*)d_in[18];
    const float* fl_b2  = (const float*)d_in[19];
    const float* fr_w   = (const float*)d_in[20];
    const float* fr_b   = (const float*)d_in[21];
    float* out = (float*)d_out;

    float *p_hw1, *p_h1raw, *p_feat1, *p_gsfeat, *p_lev;
    cudaGetSymbolAddress((void**)&p_hw1,    g_hw1);
    cudaGetSymbolAddress((void**)&p_h1raw,  g_h1raw);
    cudaGetSymbolAddress((void**)&p_feat1,  g_feat1);
    cudaGetSymbolAddress((void**)&p_gsfeat, g_gsfeat);
    cudaGetSymbolAddress((void**)&p_lev,    g_lev);

    // 1. pack head conv1 weights, zero partials
    pack_heads_kernel<<<72, 256>>>(rot_w1, scl_w1, opa_w1, rot_b1, scl_b1, opa_b1);
    zero_h1raw_kernel<<<480, 256>>>();

    // 2. head conv1: 128->16, edge pad, cin-split 4 (atomic partials), then gelu
    conv3x3_t<128, 1, 0, 4><<<dim3(5, 6, 4), 128>>>(init_feature, p_hw1, nullptr, p_h1raw);
    h1_epilogue_kernel<<<480, 256>>>();

    // 3. feature convs: fl1 128->128 reflect ELU, fl2 128->64 reflect ELU
    conv3x3_t<128, 0, 1, 1><<<dim3(5, 6, 8), 128>>>(init_feature, fl_w1, fl_b1, p_feat1);
    conv3x3_t<128, 0, 1, 1><<<dim3(5, 6, 4), 128>>>(p_feat1, fl_w2, fl_b2, p_gsfeat);

    // 4. head conv2 + per-gaussian precompute
    heads2_kernel<<<30, 256>>>(disp, invK, Kmat, rot_w2, rot_b2, scl_w2, scl_b2, opa_w2, opa_b2);

    // 5. depth sort + gather sorted SoA
    sort_kernel<<<1, 1024>>>();
    gather_kernel<<<1920, 256>>>();

    // 6. rasterize
    raster_kernel<<<480, 512>>>();

    // 7. final conv: 64->128 reflect ELU -> out
    conv3x3_t<64, 0, 1, 1><<<dim3(5, 6, 8), 128>>>(p_lev, fr_w, fr_b, out);
}